// round 7
// baseline (speedup 1.0000x reference)
#include <cuda_runtime.h>
#include <cuda_fp16.h>
#include <cstdint>

// ---------------------------------------------------------------------------
// Problem dims (fixed)
// ---------------------------------------------------------------------------
#define Bsz 8192
#define Tsz 20
#define Hsz 256
#define Psz 15
#define NG  1024   // 4*H gates

// ---------------------------------------------------------------------------
// Static device scratch (no runtime allocation allowed)
// ---------------------------------------------------------------------------
__device__ __half g_h1[(size_t)Tsz * Bsz * 128];     // relu(x@Wi+b): hi[0:64) lo[64:128) per (t,b)
__device__ __half g_h[2][(size_t)Bsz * 512];         // h state: hi[0:256) lo[256:512)
__device__ float  g_c[(size_t)Bsz * Hsz];            // c state fp32
__device__ float  g_z[(size_t)Bsz * NG];             // GEMM output scratch
__device__ float  g_D0[(size_t)Bsz * NG];            // enc_h @ dec_k (constant decoder term)
__device__ float  g_dec[(size_t)Bsz * Psz * Hsz];    // decoder h outputs
__device__ __half g_We [960 * NG];                   // [ [enc_k;enc_rk]_hi ; _lo ; _hi ]
__device__ __half g_Wdr[768 * NG];                   // [ dec_rk_hi ; lo ; hi ]
__device__ __half g_Wdi[768 * NG];                   // [ dec_k_hi  ; lo ; hi ]

// ---------------------------------------------------------------------------
// Weight packing (runs inside the graph; cheap)
// ---------------------------------------------------------------------------
__global__ void k_pack_enc(const float* __restrict__ ek, const float* __restrict__ erk) {
    int idx = blockIdx.x * blockDim.x + threadIdx.x;     // 320*1024
    if (idx >= 320 * NG) return;
    int r = idx >> 10, n = idx & 1023;
    float w = (r < 64) ? ek[r * NG + n] : erk[(r - 64) * NG + n];
    __half hi = __float2half_rn(w);
    __half lo = __float2half_rn(w - __half2float(hi));
    g_We[idx] = hi;
    g_We[320 * NG + idx] = lo;
    g_We[640 * NG + idx] = hi;
}

__global__ void k_pack_256(const float* __restrict__ w, int sel) {
    int idx = blockIdx.x * blockDim.x + threadIdx.x;     // 256*1024
    if (idx >= 256 * NG) return;
    __half* dst = sel ? g_Wdi : g_Wdr;
    float v = w[idx];
    __half hi = __float2half_rn(v);
    __half lo = __float2half_rn(v - __half2float(hi));
    dst[idx] = hi;
    dst[256 * NG + idx] = lo;
    dst[512 * NG + idx] = hi;
}

// ---------------------------------------------------------------------------
// Input projection: h1 = relu(x @ w_in_k + w_in_b), hi/lo split, all 20 steps
// ---------------------------------------------------------------------------
__global__ void k_inproj(const float* __restrict__ x, const float* __restrict__ wk,
                         const float* __restrict__ wb) {
    __shared__ float ws[8 * 64];
    __shared__ float xs[4][8];
    int tid = threadIdx.x;                 // 256 threads
    ws[tid] = wk[tid];
    ws[tid + 256] = wk[tid + 256];
    int rowbase = blockIdx.x * 4;
    if (tid < 32) xs[tid >> 3][tid & 7] = x[(size_t)(rowbase + (tid >> 3)) * 8 + (tid & 7)];
    __syncthreads();
    int r = tid >> 6, n = tid & 63;
    int row = rowbase + r;                 // row = b*20 + t
    float acc = wb[n];
#pragma unroll
    for (int k = 0; k < 8; k++) acc = fmaf(xs[r][k], ws[k * 64 + n], acc);
    acc = fmaxf(acc, 0.f);
    __half hi = __float2half_rn(acc);
    __half lo = __float2half_rn(acc - __half2float(hi));
    int b = row / 20, t = row - b * 20;
    size_t d = ((size_t)t * Bsz + b) * 128 + n;
    g_h1[d] = hi;
    g_h1[d + 64] = lo;
}

// ---------------------------------------------------------------------------
// State init
// ---------------------------------------------------------------------------
__global__ void k_init(int zero_both_h) {
    int idx = blockIdx.x * blockDim.x + threadIdx.x;     // covers Bsz*512
    if (idx < Bsz * Hsz) g_c[idx] = 0.f;
    if (idx < Bsz * 512) {
        g_h[0][idx] = __float2half_rn(0.f);
        if (zero_both_h) g_h[1][idx] = __float2half_rn(0.f);
    }
}

// ---------------------------------------------------------------------------
// GEMM: C[8192,1024] = A(segmented fp16 hi/lo, 3-term) @ Bw(packed fp16)
//   KT=30 (encoder: a=[h1|h], K=960)  KT=24 (decoder/D0: a=h, K=768)
//   mma.sync m16n8k16, BM=128 BN=128 BK=32, 256 thr, 2-stage cp.async
// ---------------------------------------------------------------------------
#define BM   128
#define BN   128
#define ASTR 40     // halfs per A smem row (32 + 8 pad)
#define BSTR 136    // halfs per B smem row (128 + 8 pad)

__global__ void __launch_bounds__(256, 2) k_gemm(int abuf, int t, int wsel, int csel, int KT) {
    __shared__ __align__(16) __half sA[2][BM * ASTR];
    __shared__ __align__(16) __half sB[2][32 * BSTR];

    const __half* __restrict__ Ah  = g_h[abuf];
    const __half* __restrict__ Ah1 = (t >= 0) ? (g_h1 + (size_t)t * Bsz * 128) : (const __half*)0;
    const __half* __restrict__ Bw  = (wsel == 0) ? g_We : (wsel == 1) ? g_Wdr : g_Wdi;
    float* __restrict__ Cz = csel ? g_D0 : g_z;

    const int tid  = threadIdx.x;
    const int lane = tid & 31;
    const int warp = tid >> 5;
    const int mblk = blockIdx.x * BM;       // gridDim.x = 64
    const int nblk = blockIdx.y * BN;       // gridDim.y = 8
    const int wm = (warp >> 1) * 32;
    const int wn = (warp & 1) * 64;

    float acc[2][8][4];
#pragma unroll
    for (int a = 0; a < 2; a++)
#pragma unroll
        for (int b = 0; b < 8; b++)
#pragma unroll
            for (int c = 0; c < 4; c++) acc[a][b][c] = 0.f;

    auto loadTile = [&](int kt, int s) {
        // A segment mapping: logical k-tile -> physical source/col
        const __half* src;
        int stride, col;
        if (KT == 30) {
            int p = (kt < 10) ? kt : kt - 10;            // 0..19
            if (p < 2)       { src = Ah1; stride = 128; col = p * 32; }
            else if (p < 10) { src = Ah;  stride = 512; col = (p - 2) * 32; }
            else if (p < 12) { src = Ah1; stride = 128; col = 64 + (p - 10) * 32; }
            else             { src = Ah;  stride = 512; col = 256 + (p - 12) * 32; }
        } else {
            int p = (kt < 8) ? kt : kt - 8;              // 0..15
            src = Ah; stride = 512; col = p * 32;
        }
#pragma unroll
        for (int j = 0; j < 2; j++) {                    // A: 512 16B chunks
            int ci = tid + j * 256;
            int row = ci >> 2, c16 = ci & 3;
            const __half* g = src + (size_t)(mblk + row) * stride + col + c16 * 8;
            uint32_t sa = (uint32_t)__cvta_generic_to_shared(&sA[s][row * ASTR + c16 * 8]);
            asm volatile("cp.async.cg.shared.global [%0], [%1], 16;\n" :: "r"(sa), "l"(g));
        }
#pragma unroll
        for (int j = 0; j < 2; j++) {                    // B: 512 16B chunks
            int ci = tid + j * 256;
            int row = ci >> 4, c16 = ci & 15;
            const __half* g = Bw + (size_t)(kt * 32 + row) * NG + nblk + c16 * 8;
            uint32_t sb = (uint32_t)__cvta_generic_to_shared(&sB[s][row * BSTR + c16 * 8]);
            asm volatile("cp.async.cg.shared.global [%0], [%1], 16;\n" :: "r"(sb), "l"(g));
        }
        asm volatile("cp.async.commit_group;\n");
    };

    loadTile(0, 0);
    for (int kt = 0; kt < KT; kt++) {
        int s = kt & 1;
        asm volatile("cp.async.wait_group 0;\n");
        __syncthreads();
        if (kt + 1 < KT) loadTile(kt + 1, s ^ 1);
#pragma unroll
        for (int ks = 0; ks < 2; ks++) {
            uint32_t a[2][4], bf[4][4];
#pragma unroll
            for (int mf = 0; mf < 2; mf++) {
                uint32_t ad = (uint32_t)__cvta_generic_to_shared(
                    &sA[s][(wm + mf * 16 + (lane & 15)) * ASTR + ks * 16 + (lane >> 4) * 8]);
                asm volatile("ldmatrix.sync.aligned.x4.m8n8.shared.b16 {%0,%1,%2,%3}, [%4];\n"
                             : "=r"(a[mf][0]), "=r"(a[mf][1]), "=r"(a[mf][2]), "=r"(a[mf][3])
                             : "r"(ad));
            }
#pragma unroll
            for (int ng = 0; ng < 4; ng++) {
                uint32_t ad = (uint32_t)__cvta_generic_to_shared(
                    &sB[s][(ks * 16 + ((lane >> 3) & 1) * 8 + (lane & 7)) * BSTR
                           + wn + ng * 16 + (lane >> 4) * 8]);
                asm volatile("ldmatrix.sync.aligned.x4.trans.m8n8.shared.b16 {%0,%1,%2,%3}, [%4];\n"
                             : "=r"(bf[ng][0]), "=r"(bf[ng][1]), "=r"(bf[ng][2]), "=r"(bf[ng][3])
                             : "r"(ad));
            }
#pragma unroll
            for (int mf = 0; mf < 2; mf++)
#pragma unroll
                for (int j = 0; j < 8; j++) {
                    uint32_t b0 = bf[j >> 1][(j & 1) * 2], b1 = bf[j >> 1][(j & 1) * 2 + 1];
                    asm volatile(
                        "mma.sync.aligned.m16n8k16.row.col.f32.f16.f16.f32 "
                        "{%0,%1,%2,%3}, {%4,%5,%6,%7}, {%8,%9}, {%0,%1,%2,%3};\n"
                        : "+f"(acc[mf][j][0]), "+f"(acc[mf][j][1]),
                          "+f"(acc[mf][j][2]), "+f"(acc[mf][j][3])
                        : "r"(a[mf][0]), "r"(a[mf][1]), "r"(a[mf][2]), "r"(a[mf][3]),
                          "r"(b0), "r"(b1));
                }
        }
    }

#pragma unroll
    for (int mf = 0; mf < 2; mf++) {
        int r0 = mblk + wm + mf * 16 + (lane >> 2);
#pragma unroll
        for (int j = 0; j < 8; j++) {
            int n = nblk + wn + j * 8 + (lane & 3) * 2;
            *(float2*)&Cz[(size_t)r0 * NG + n]       = make_float2(acc[mf][j][0], acc[mf][j][1]);
            *(float2*)&Cz[(size_t)(r0 + 8) * NG + n] = make_float2(acc[mf][j][2], acc[mf][j][3]);
        }
    }
}

// ---------------------------------------------------------------------------
// LSTM cell pointwise: gates from z (+D0) (+bias), update c, write h (hi/lo)
// ---------------------------------------------------------------------------
__device__ __forceinline__ float sigm_(float x) { return 1.f / (1.f + __expf(-x)); }
__device__ __forceinline__ float tanh_(float x) {
    float e = __expf(-2.f * fabsf(x));
    float t = (1.f - e) / (1.f + e);
    return copysignf(t, x);
}

__global__ void k_cell(int useD0, const float* __restrict__ bias, int dstbuf, int pstep) {
    int idx = blockIdx.x * blockDim.x + threadIdx.x;   // Bsz*Hsz
    if (idx >= Bsz * Hsz) return;
    int b = idx >> 8, u = idx & 255;
    size_t zb = (size_t)b * NG;
    float zi = g_z[zb + u], zf = g_z[zb + 256 + u];
    float zg = g_z[zb + 512 + u], zo = g_z[zb + 768 + u];
    if (useD0) {
        zi += g_D0[zb + u];       zf += g_D0[zb + 256 + u];
        zg += g_D0[zb + 512 + u]; zo += g_D0[zb + 768 + u];
    }
    zi += bias[u]; zf += bias[256 + u]; zg += bias[512 + u]; zo += bias[768 + u];
    float i = sigm_(zi), f = sigm_(zf), g = tanh_(zg), o = sigm_(zo);
    float cn = f * g_c[idx] + i * g;
    g_c[idx] = cn;
    float h = o * tanh_(cn);
    __half hi = __float2half_rn(h);
    __half lo = __float2half_rn(h - __half2float(hi));
    __half* hd = g_h[dstbuf];
    hd[(size_t)b * 512 + u]       = hi;
    hd[(size_t)b * 512 + 256 + u] = lo;
    if (pstep >= 0) g_dec[((size_t)b * Psz + pstep) * Hsz + u] = h;
}

// ---------------------------------------------------------------------------
// Output heads: warp per (b,p) row of g_dec
// ---------------------------------------------------------------------------
__global__ void k_heads(const float* __restrict__ mk, const float* __restrict__ mb,
                        const float* __restrict__ lk, const float* __restrict__ lb,
                        float* __restrict__ out) {
    int gw = (blockIdx.x * blockDim.x + threadIdx.x) >> 5;
    int lane = threadIdx.x & 31;
    if (gw >= Bsz * Psz) return;
    const float* d = g_dec + (size_t)gw * Hsz + lane * 8;
    float m0 = 0.f, m1 = 0.f, v0 = 0.f, v1 = 0.f;
#pragma unroll
    for (int i = 0; i < 8; i++) {
        float dv = d[i];
        int k = lane * 8 + i;
        m0 = fmaf(dv, mk[2 * k],     m0);
        m1 = fmaf(dv, mk[2 * k + 1], m1);
        v0 = fmaf(dv, lk[2 * k],     v0);
        v1 = fmaf(dv, lk[2 * k + 1], v1);
    }
#pragma unroll
    for (int off = 16; off; off >>= 1) {
        m0 += __shfl_xor_sync(0xFFFFFFFFu, m0, off);
        m1 += __shfl_xor_sync(0xFFFFFFFFu, m1, off);
        v0 += __shfl_xor_sync(0xFFFFFFFFu, v0, off);
        v1 += __shfl_xor_sync(0xFFFFFFFFu, v1, off);
    }
    if (lane == 0) {
        float4 r = make_float4(m0 + mb[0], m1 + mb[1],
                               fmaxf(v0 + lb[0], 0.f), fmaxf(v1 + lb[1], 0.f));
        *(float4*)&out[(size_t)gw * 4] = r;
    }
}

// ---------------------------------------------------------------------------
// Launch
// ---------------------------------------------------------------------------
extern "C" void kernel_launch(void* const* d_in, const int* in_sizes, int n_in,
                              void* d_out, int out_size) {
    (void)in_sizes; (void)n_in; (void)out_size;
    const float* x      = (const float*)d_in[0];
    const float* w_in_k = (const float*)d_in[1];
    const float* w_in_b = (const float*)d_in[2];
    const float* enc_k  = (const float*)d_in[3];
    const float* enc_rk = (const float*)d_in[4];
    const float* enc_b  = (const float*)d_in[5];
    const float* dec_k  = (const float*)d_in[6];
    const float* dec_rk = (const float*)d_in[7];
    const float* dec_b  = (const float*)d_in[8];
    const float* mean_k = (const float*)d_in[9];
    const float* mean_b = (const float*)d_in[10];
    const float* lv_k   = (const float*)d_in[11];
    const float* lv_b   = (const float*)d_in[12];
    float* out = (float*)d_out;

    const dim3 gGrid(64, 8), gBlk(256);

    k_pack_enc<<<(320 * NG + 255) / 256, 256>>>(enc_k, enc_rk);
    k_pack_256<<<(256 * NG + 255) / 256, 256>>>(dec_rk, 0);
    k_pack_256<<<(256 * NG + 255) / 256, 256>>>(dec_k, 1);
    k_inproj<<<(Bsz * Tsz) / 4, 256>>>(x, w_in_k, w_in_b);
    k_init<<<(Bsz * 512 + 255) / 256, 256>>>(1);

    // Encoder: 20 steps
    for (int t = 0; t < Tsz; t++) {
        k_gemm<<<gGrid, gBlk>>>(t & 1, t, 0, 0, 30);
        k_cell<<<(Bsz * Hsz) / 256, 256>>>(0, enc_b, (t + 1) & 1, -1);
    }
    // D0 = enc_h @ dec_k  (enc final h is in buffer 0)
    k_gemm<<<gGrid, gBlk>>>(0, -1, 2, 1, 24);
    // Reset state for decoder
    k_init<<<(Bsz * 512 + 255) / 256, 256>>>(0);
    // Decoder: 15 steps
    for (int d = 0; d < Psz; d++) {
        k_gemm<<<gGrid, gBlk>>>(d & 1, -1, 1, 0, 24);
        k_cell<<<(Bsz * Hsz) / 256, 256>>>(1, dec_b, (d + 1) & 1, d);
    }
    k_heads<<<(Bsz * Psz * 32 + 255) / 256, 256>>>(mean_k, mean_b, lv_k, lv_b, out);
}